// round 13
// baseline (speedup 1.0000x reference)
#include <cuda_runtime.h>
#include <cuda_bf16.h>
#include <cstdint>
#include <math.h>

using bf16 = __nv_bfloat16;

#define BATCH 4
#define SEQ   4096
#define DIM   768
#define QKV   (3 * DIM)                     // 2304
#define NTOK  (BATCH * SEQ)                 // 16384
#define NTD   ((size_t)NTOK * DIM)
#define NTQ   ((size_t)NTOK * QKV)
#define WSZ   ((size_t)DIM * DIM)
#define SSZ   ((size_t)BATCH * SEQ * SEQ)

// ---------------- device scratch (allocation-free rule) ----------------
__device__ bf16  g_xh[NTD], g_xl[NTD];
__device__ bf16  g_wch[3 * WSZ], g_wcl[3 * WSZ];   // [Wq;Wk;Wv] hi/lo
__device__ float g_bias[QKV];
__device__ bf16  g_qkvh[NTQ], g_qkvl[NTQ];         // fused q|k|v, ld = 2304
__device__ bf16  g_vth[NTD], g_vtl[NTD];           // V transposed: [b][dim][seq]
__device__ float g_s[SSZ];                         // scores fp32
__device__ bf16  g_ph[SSZ], g_pl[SSZ];             // softmax probs hi/lo

__device__ __forceinline__ uint32_t smem_u32(const void* p) {
    uint32_t a;
    asm("{ .reg .u64 t; cvta.to.shared.u64 t, %1; cvt.u32.u64 %0, t; }" : "=r"(a) : "l"(p));
    return a;
}

__device__ __forceinline__ void ldsm4(uint32_t* r, uint32_t addr) {
    asm volatile("ldmatrix.sync.aligned.m8n8.x4.shared.b16 {%0,%1,%2,%3}, [%4];"
                 : "=r"(r[0]), "=r"(r[1]), "=r"(r[2]), "=r"(r[3]) : "r"(addr));
}
__device__ __forceinline__ void mma16816(float* d, const uint32_t* a, const uint32_t* b) {
    asm volatile("mma.sync.aligned.m16n8k16.row.col.f32.bf16.bf16.f32 "
                 "{%0,%1,%2,%3}, {%4,%5,%6,%7}, {%8,%9}, {%0,%1,%2,%3};"
                 : "+f"(d[0]), "+f"(d[1]), "+f"(d[2]), "+f"(d[3])
                 : "r"(a[0]), "r"(a[1]), "r"(a[2]), "r"(a[3]), "r"(b[0]), "r"(b[1]));
}

__device__ __forceinline__ uint32_t pack_bf2(float a, float b) {
    __nv_bfloat162 t = __floats2bfloat162_rn(a, b);
    return *(uint32_t*)&t;
}

// Fast exp on the FMA pipe (no MUFU). |err| ~ 5e-9 over the used range.
// x <= 0 here (post max-subtraction); clamp protects the exponent-bit scale.
__device__ __forceinline__ float fexp(float x) {
    x = fmaxf(x, -80.0f);
    float n = rintf(x * 1.4426950408889634f);       // round(x / ln2)
    float t = fmaf(n, -0.6931471805599453f, x);     // t = x - n*ln2, |t| <= 0.3466
    float p = 1.9841270e-4f;                        // 1/7!
    p = fmaf(p, t, 1.3888889e-3f);                  // 1/6!
    p = fmaf(p, t, 8.3333333e-3f);                  // 1/5!
    p = fmaf(p, t, 4.1666667e-2f);                  // 1/4!
    p = fmaf(p, t, 1.6666667e-1f);                  // 1/3!
    p = fmaf(p, t, 0.5f);
    p = fmaf(p, t, 1.0f);
    p = fmaf(p, t, 1.0f);
    float s = __int_as_float(((int)n + 127) << 23); // 2^n
    return p * s;
}

// ---------------------------------------------------------------------------
// NT GEMM via raw mma.sync + ldmatrix, 3-pass bf16 hi/lo split:
//   acc[M,N] = Ah*Bh^T + Ah*Bl^T + Al*Bh^T
// MODE 0: C = alpha * acc (fp32)
// MODE 1: t = acc + bias[col]; Oh/Ol = hi/lo bf16 split of t  (ld = ldc)
// CTA tile 128x256, BK=64, 256 threads (8 warps 2x4, warp tile 64x64).
// 3-stage cp.async pipeline; smem rows 128B, XOR-16B swizzle;
// double-buffered ldmatrix fragments inside the k-tile.
// Requires M%128==0, N%256==0, K%64==0, 16B-aligned rows.
// ---------------------------------------------------------------------------
#define BM 128
#define BN 256
#define BK 64
#define A_BYTES (BM * 128)                 // 16384
#define B_BYTES (BN * 128)                 // 32768
#define STAGE_BYTES (A_BYTES + B_BYTES)    // 49152
#define NSTAGE 3
#define GEMM_SMEM (NSTAGE * STAGE_BYTES)   // 147456

template <int MODE>
__global__ __launch_bounds__(256, 1) void gemm_mma(
    const bf16* __restrict__ Ah, const bf16* __restrict__ Al,
    const bf16* __restrict__ Bh, const bf16* __restrict__ Bl,
    float* __restrict__ C, const float* __restrict__ bias,
    bf16* __restrict__ Oh, bf16* __restrict__ Ol,
    int K, int lda, int ldb, int ldc, float alpha,
    size_t sA, size_t sB, size_t sC)
{
    extern __shared__ char smem[];
    const uint32_t sbase = smem_u32(smem);

    const int tid = threadIdx.x;
    const int wid = tid >> 5;
    const int l   = tid & 31;
    const int m0 = blockIdx.x * BM;
    const int n0 = blockIdx.y * BN;
    const int z  = blockIdx.z;
    Ah += (size_t)z * sA; Al += (size_t)z * sA;
    Bh += (size_t)z * sB; Bl += (size_t)z * sB;

    const int NCP = K / BK;
    const int NT  = 3 * NCP;      // hi*hi, hi*lo, lo*hi

    const int wm = (wid >> 2) * 64;   // warp M offset in CTA tile
    const int wn = (wid & 3) * 64;    // warp N offset

    float acc[4][8][4];
#pragma unroll
    for (int i = 0; i < 4; i++)
#pragma unroll
        for (int j = 0; j < 8; j++)
#pragma unroll
            for (int t = 0; t < 4; t++) acc[i][j][t] = 0.0f;

    auto load_stage = [&](int s, int kt) {
        const int p  = kt / NCP;
        const int kc = (kt - p * NCP) * BK;
        const bf16* A = (p < 2) ? Ah : Al;
        const bf16* B = (p == 1) ? Bl : Bh;
        const uint32_t ast = sbase + s * STAGE_BYTES;
        const uint32_t bst = ast + A_BYTES;
#pragma unroll
        for (int h = 0; h < 4; h++) {            // A: 1024 16B chunks
            const int c = tid + h * 256;
            const int r = c >> 3, cc = c & 7;
            const uint32_t da = ast + r * 128 + ((cc * 16) ^ ((r & 7) * 16));
            const bf16* ga = A + (size_t)(m0 + r) * lda + kc + cc * 8;
            asm volatile("cp.async.cg.shared.global [%0], [%1], 16;" :: "r"(da), "l"(ga));
        }
#pragma unroll
        for (int h = 0; h < 8; h++) {            // B: 2048 16B chunks
            const int c = tid + h * 256;
            const int r = c >> 3, cc = c & 7;
            const uint32_t db = bst + r * 128 + ((cc * 16) ^ ((r & 7) * 16));
            const bf16* gb = B + (size_t)(n0 + r) * ldb + kc + cc * 8;
            asm volatile("cp.async.cg.shared.global [%0], [%1], 16;" :: "r"(db), "l"(gb));
        }
        asm volatile("cp.async.commit_group;" ::: "memory");
    };

#pragma unroll
    for (int s = 0; s < NSTAGE - 1; s++) load_stage(s, s);

    // per-lane ldmatrix address components (within stage)
    const uint32_t xorv = (l & 7) * 16;
    const int arow = wm + (l & 15);               // + 16*i
    const uint32_t acolb = (l >> 4) * 16;         // + 32*kk
    const int brow = wn + (l & 7) + (l >> 4) * 8; // + 16*j
    const uint32_t bcolb = ((l >> 3) & 1) * 16;   // + 32*kk

    for (int kt = 0; kt < NT; kt++) {
        const int cur = kt % NSTAGE;
        asm volatile("cp.async.wait_group %0;" :: "n"(NSTAGE - 2) : "memory");
        __syncthreads();
        if (kt + NSTAGE - 1 < NT) load_stage((kt + NSTAGE - 1) % NSTAGE, kt + NSTAGE - 1);

        const uint32_t ast = sbase + cur * STAGE_BYTES;
        const uint32_t bst = ast + A_BYTES;

        // double-buffered fragments: prefetch kk+1 while issuing kk's MMAs
        uint32_t af[2][4][4], bf[2][4][4];
#pragma unroll
        for (int i = 0; i < 4; i++)
            ldsm4(af[0][i], ast + (arow + 16 * i) * 128 + (acolb ^ xorv));
#pragma unroll
        for (int j = 0; j < 4; j++)
            ldsm4(bf[0][j], bst + (brow + 16 * j) * 128 + (bcolb ^ xorv));

#pragma unroll
        for (int kk = 0; kk < 4; kk++) {         // 4 x k16 per BK=64
            const int cb = kk & 1, nb = cb ^ 1;
            if (kk < 3) {
#pragma unroll
                for (int i = 0; i < 4; i++)
                    ldsm4(af[nb][i],
                          ast + (arow + 16 * i) * 128 + ((acolb + 32 * (kk + 1)) ^ xorv));
#pragma unroll
                for (int j = 0; j < 4; j++)
                    ldsm4(bf[nb][j],
                          bst + (brow + 16 * j) * 128 + ((bcolb + 32 * (kk + 1)) ^ xorv));
            }
#pragma unroll
            for (int i = 0; i < 4; i++)
#pragma unroll
                for (int j = 0; j < 8; j++)
                    mma16816(acc[i][j], af[cb][i], &bf[cb][j >> 1][(j & 1) * 2]);
        }
        // no trailing barrier: next iteration's top barrier protects the ring
    }

    // epilogue: c0,c1 -> (row, col..col+1); c2,c3 -> (row+8, ...)
    const int er = l >> 2, ec = (l & 3) * 2;
#pragma unroll
    for (int i = 0; i < 4; i++) {
        const int row = m0 + wm + 16 * i + er;
#pragma unroll
        for (int j = 0; j < 8; j++) {
            const int col = n0 + wn + 8 * j + ec;
            if (MODE == 0) {
                float* Cz = C + (size_t)z * sC;
                float2 v0 = {acc[i][j][0] * alpha, acc[i][j][1] * alpha};
                float2 v1 = {acc[i][j][2] * alpha, acc[i][j][3] * alpha};
                *(float2*)(Cz + (size_t)row * ldc + col) = v0;
                *(float2*)(Cz + (size_t)(row + 8) * ldc + col) = v1;
            } else {
                const float b0 = bias[col], b1 = bias[col + 1];
                float t00 = acc[i][j][0] + b0, t01 = acc[i][j][1] + b1;
                float t10 = acc[i][j][2] + b0, t11 = acc[i][j][3] + b1;
                bf16 h00 = __float2bfloat16(t00), h01 = __float2bfloat16(t01);
                bf16 h10 = __float2bfloat16(t10), h11 = __float2bfloat16(t11);
                float l00 = t00 - __bfloat162float(h00), l01 = t01 - __bfloat162float(h01);
                float l10 = t10 - __bfloat162float(h10), l11 = t11 - __bfloat162float(h11);
                uint32_t hp0, hp1;
                { __nv_bfloat162 t = {h00, h01}; hp0 = *(uint32_t*)&t; }
                { __nv_bfloat162 t = {h10, h11}; hp1 = *(uint32_t*)&t; }
                *(uint32_t*)(Oh + (size_t)row * ldc + col) = hp0;
                *(uint32_t*)(Oh + (size_t)(row + 8) * ldc + col) = hp1;
                *(uint32_t*)(Ol + (size_t)row * ldc + col) = pack_bf2(l00, l01);
                *(uint32_t*)(Ol + (size_t)(row + 8) * ldc + col) = pack_bf2(l10, l11);
            }
        }
    }
}

// ---------------- fp32 -> bf16 hi/lo split ----------------
__global__ __launch_bounds__(256) void split_k(const float* __restrict__ in,
                                               bf16* __restrict__ h, bf16* __restrict__ l,
                                               int n4)
{
    int i = blockIdx.x * blockDim.x + threadIdx.x;
    if (i >= n4) return;
    float4 v = ((const float4*)in)[i];
    float vv[4] = {v.x, v.y, v.z, v.w};
    union { unsigned short u[4]; uint2 q; } hh, ll;
#pragma unroll
    for (int e = 0; e < 4; e++) {
        bf16 hb = __float2bfloat16(vv[e]);
        bf16 lb = __float2bfloat16(vv[e] - __bfloat162float(hb));
        hh.u[e] = *(unsigned short*)&hb;
        ll.u[e] = *(unsigned short*)&lb;
    }
    ((uint2*)h)[i] = hh.q;
    ((uint2*)l)[i] = ll.q;
}

// ---------------- concat bias [bq|bk|bv] ----------------
__global__ void concat_bias_k(const float* __restrict__ bq, const float* __restrict__ bk,
                              const float* __restrict__ bv, float* __restrict__ o)
{
    int i = blockIdx.x * blockDim.x + threadIdx.x;
    if (i >= QKV) return;
    float v;
    if (i < DIM) v = bq[i];
    else if (i < 2 * DIM) v = bk[i - DIM];
    else v = bv[i - 2 * DIM];
    o[i] = v;
}

// ---------------- transpose V[b][s][d](ldin) -> Vt[b][d][s] (hi & lo) ----------------
__global__ void transpose_k(const bf16* __restrict__ vh, const bf16* __restrict__ vl,
                            bf16* __restrict__ th, bf16* __restrict__ tl, int ldin)
{
    __shared__ bf16 sh[32][33], sl[32][33];
    const int z = blockIdx.z;
    const size_t ibi = (size_t)z * SEQ * ldin;
    const size_t ibo = (size_t)z * SEQ * DIM;
    const int d0 = blockIdx.x * 32, s0 = blockIdx.y * 32;
    const int tx = threadIdx.x, ty = threadIdx.y;
#pragma unroll
    for (int i = 0; i < 32; i += 8) {
        sh[ty + i][tx] = vh[ibi + (size_t)(s0 + ty + i) * ldin + d0 + tx];
        sl[ty + i][tx] = vl[ibi + (size_t)(s0 + ty + i) * ldin + d0 + tx];
    }
    __syncthreads();
#pragma unroll
    for (int i = 0; i < 32; i += 8) {
        th[ibo + (size_t)(d0 + ty + i) * SEQ + s0 + tx] = sh[tx][ty + i];
        tl[ibo + (size_t)(d0 + ty + i) * SEQ + s0 + tx] = sl[tx][ty + i];
    }
}

// ---------------- softmax: fp32 scores row -> P hi/lo bf16 ----------------
__global__ __launch_bounds__(256) void softmax_k(const float* __restrict__ S,
                                                 bf16* __restrict__ ph, bf16* __restrict__ pl)
{
    const size_t rb = (size_t)blockIdx.x * SEQ;
    const float* p = S + rb;
    const int tid = threadIdx.x;

    float4 v[4];
#pragma unroll
    for (int i = 0; i < 4; i++) v[i] = *(const float4*)(p + tid * 4 + i * 1024);

    float m = -INFINITY;
#pragma unroll
    for (int i = 0; i < 4; i++)
        m = fmaxf(m, fmaxf(fmaxf(v[i].x, v[i].y), fmaxf(v[i].z, v[i].w)));

    __shared__ float red[256];
    red[tid] = m; __syncthreads();
#pragma unroll
    for (int s = 128; s > 0; s >>= 1) {
        if (tid < s) red[tid] = fmaxf(red[tid], red[tid + s]);
        __syncthreads();
    }
    m = red[0]; __syncthreads();

    float sum = 0.0f;
#pragma unroll
    for (int i = 0; i < 4; i++) {
        v[i].x = fexp(v[i].x - m); v[i].y = fexp(v[i].y - m);
        v[i].z = fexp(v[i].z - m); v[i].w = fexp(v[i].w - m);
        sum += v[i].x + v[i].y + v[i].z + v[i].w;
    }
    red[tid] = sum; __syncthreads();
#pragma unroll
    for (int s = 128; s > 0; s >>= 1) {
        if (tid < s) red[tid] += red[tid + s];
        __syncthreads();
    }
    const float inv = 1.0f / red[0];

#pragma unroll
    for (int i = 0; i < 4; i++) {
        float vv[4] = {v[i].x * inv, v[i].y * inv, v[i].z * inv, v[i].w * inv};
        union { unsigned short u[4]; uint2 q; } hh, ll;
#pragma unroll
        for (int e = 0; e < 4; e++) {
            bf16 hb = __float2bfloat16(vv[e]);
            bf16 lb = __float2bfloat16(vv[e] - __bfloat162float(hb));
            hh.u[e] = *(unsigned short*)&hb;
            ll.u[e] = *(unsigned short*)&lb;
        }
        *(uint2*)(ph + rb + tid * 4 + i * 1024) = hh.q;
        *(uint2*)(pl + rb + tid * 4 + i * 1024) = ll.q;
    }
}

// ---------------- launch ----------------
extern "C" void kernel_launch(void* const* d_in, const int* in_sizes, int n_in,
                              void* d_out, int out_size)
{
    const float* x  = (const float*)d_in[0];
    const float* Wq = (const float*)d_in[1];
    const float* bq = (const float*)d_in[2];
    const float* Wk = (const float*)d_in[3];
    const float* bk = (const float*)d_in[4];
    const float* Wv = (const float*)d_in[5];
    const float* bv = (const float*)d_in[6];
    float* out = (float*)d_out;

    bf16 *xh, *xl, *wch, *wcl, *qkvh, *qkvl, *vth, *vtl, *pph, *ppl;
    float *sc, *bias;
    cudaGetSymbolAddress((void**)&xh, g_xh);     cudaGetSymbolAddress((void**)&xl, g_xl);
    cudaGetSymbolAddress((void**)&wch, g_wch);   cudaGetSymbolAddress((void**)&wcl, g_wcl);
    cudaGetSymbolAddress((void**)&qkvh, g_qkvh); cudaGetSymbolAddress((void**)&qkvl, g_qkvl);
    cudaGetSymbolAddress((void**)&vth, g_vth);   cudaGetSymbolAddress((void**)&vtl, g_vtl);
    cudaGetSymbolAddress((void**)&pph, g_ph);    cudaGetSymbolAddress((void**)&ppl, g_pl);
    cudaGetSymbolAddress((void**)&sc, g_s);      cudaGetSymbolAddress((void**)&bias, g_bias);

    cudaFuncSetAttribute(gemm_mma<0>, cudaFuncAttributeMaxDynamicSharedMemorySize, GEMM_SMEM);
    cudaFuncSetAttribute(gemm_mma<1>, cudaFuncAttributeMaxDynamicSharedMemorySize, GEMM_SMEM);

    const float scale = 1.0f / sqrtf((float)DIM);

    // 1. split inputs to bf16 hi/lo (weights into concatenated [Wq;Wk;Wv])
    split_k<<<(int)(NTD / 4 + 255) / 256, 256>>>(x, xh, xl, (int)(NTD / 4));
    split_k<<<(int)(WSZ / 4 + 255) / 256, 256>>>(Wq, wch, wcl, (int)(WSZ / 4));
    split_k<<<(int)(WSZ / 4 + 255) / 256, 256>>>(Wk, wch + WSZ, wcl + WSZ, (int)(WSZ / 4));
    split_k<<<(int)(WSZ / 4 + 255) / 256, 256>>>(Wv, wch + 2 * WSZ, wcl + 2 * WSZ, (int)(WSZ / 4));
    concat_bias_k<<<(QKV + 255) / 256, 256>>>(bq, bk, bv, bias);

    // 2. fused QKV projection: [16384, 2304] = X * Wc^T + bias  (hi/lo epilogue)
    gemm_mma<1><<<dim3(NTOK / BM, QKV / BN, 1), 256, GEMM_SMEM>>>(
        xh, xl, wch, wcl, nullptr, bias, qkvh, qkvl,
        DIM, DIM, DIM, QKV, 1.0f, 0, 0, 0);

    // 3. transpose V (qkv columns 1536..2303) -> Vt[b][d][s]
    transpose_k<<<dim3(DIM / 32, SEQ / 32, BATCH), dim3(32, 8)>>>(
        qkvh + 2 * DIM, qkvl + 2 * DIM, vth, vtl, QKV);

    // 4. scores[b] = scale * Q[b] K[b]^T   (q, k are qkv slices, ld = 2304)
    gemm_mma<0><<<dim3(SEQ / BM, SEQ / BN, BATCH), 256, GEMM_SMEM>>>(
        qkvh, qkvl, qkvh + DIM, qkvl + DIM, sc, nullptr, nullptr, nullptr,
        DIM, QKV, QKV, SEQ, scale,
        (size_t)SEQ * QKV, (size_t)SEQ * QKV, (size_t)SEQ * SEQ);

    // 5. softmax rows -> P hi/lo  (FMA-pipe exp, no MUFU)
    softmax_k<<<NTOK, 256>>>(sc, pph, ppl);

    // 6. out[b] = P[b] V[b]   (B operand = Vt, K-major over seq)
    gemm_mma<0><<<dim3(SEQ / BM, DIM / BN, BATCH), 256, GEMM_SMEM>>>(
        pph, ppl, vth, vtl, out, nullptr, nullptr, nullptr,
        SEQ, SEQ, SEQ, DIM, 1.0f,
        (size_t)SEQ * SEQ, (size_t)SEQ * DIM, (size_t)SEQ * DIM);

    (void)in_sizes; (void)n_in; (void)out_size;
}

// round 14
// speedup vs baseline: 1.1038x; 1.1038x over previous
#include <cuda_runtime.h>
#include <cuda_bf16.h>
#include <cstdint>
#include <math.h>

using bf16 = __nv_bfloat16;

#define BATCH 4
#define SEQ   4096
#define DIM   768
#define QKV   (3 * DIM)                     // 2304
#define NTOK  (BATCH * SEQ)                 // 16384
#define NTD   ((size_t)NTOK * DIM)
#define NTQ   ((size_t)NTOK * QKV)
#define WSZ   ((size_t)DIM * DIM)
#define SSZ   ((size_t)BATCH * SEQ * SEQ)

// ---------------- device scratch (allocation-free rule) ----------------
__device__ bf16  g_xh[NTD], g_xl[NTD];
__device__ bf16  g_wch[3 * WSZ], g_wcl[3 * WSZ];   // [Wq;Wk;Wv] hi/lo
__device__ float g_bias[QKV];
__device__ bf16  g_qkvh[NTQ], g_qkvl[NTQ];         // fused q|k|v, ld = 2304
__device__ bf16  g_vth[NTD], g_vtl[NTD];           // V transposed: [b][dim][seq]
__device__ float g_s[SSZ];                         // scores fp32
__device__ bf16  g_ph[SSZ], g_pl[SSZ];             // softmax probs hi/lo

__device__ __forceinline__ uint32_t smem_u32(const void* p) {
    uint32_t a;
    asm("{ .reg .u64 t; cvta.to.shared.u64 t, %1; cvt.u32.u64 %0, t; }" : "=r"(a) : "l"(p));
    return a;
}

__device__ __forceinline__ void ldsm4(uint32_t* r, uint32_t addr) {
    asm volatile("ldmatrix.sync.aligned.m8n8.x4.shared.b16 {%0,%1,%2,%3}, [%4];"
                 : "=r"(r[0]), "=r"(r[1]), "=r"(r[2]), "=r"(r[3]) : "r"(addr));
}
__device__ __forceinline__ void mma16816(float* d, const uint32_t* a, const uint32_t* b) {
    asm volatile("mma.sync.aligned.m16n8k16.row.col.f32.bf16.bf16.f32 "
                 "{%0,%1,%2,%3}, {%4,%5,%6,%7}, {%8,%9}, {%0,%1,%2,%3};"
                 : "+f"(d[0]), "+f"(d[1]), "+f"(d[2]), "+f"(d[3])
                 : "r"(a[0]), "r"(a[1]), "r"(a[2]), "r"(a[3]), "r"(b[0]), "r"(b[1]));
}

__device__ __forceinline__ uint32_t pack_bf2(float a, float b) {
    __nv_bfloat162 t = __floats2bfloat162_rn(a, b);
    return *(uint32_t*)&t;
}

// Fast exp on the FMA pipe. |err| ~ 5e-9 over the used range. x <= 0 here.
__device__ __forceinline__ float fexp(float x) {
    x = fmaxf(x, -80.0f);
    float n = rintf(x * 1.4426950408889634f);
    float t = fmaf(n, -0.6931471805599453f, x);
    float p = 1.9841270e-4f;
    p = fmaf(p, t, 1.3888889e-3f);
    p = fmaf(p, t, 8.3333333e-3f);
    p = fmaf(p, t, 4.1666667e-2f);
    p = fmaf(p, t, 1.6666667e-1f);
    p = fmaf(p, t, 0.5f);
    p = fmaf(p, t, 1.0f);
    p = fmaf(p, t, 1.0f);
    float s = __int_as_float(((int)n + 127) << 23);
    return p * s;
}

// ---------------------------------------------------------------------------
// NT GEMM via raw mma.sync + ldmatrix, 3-pass bf16 hi/lo split:
//   acc[M,N] = Ah*Bh^T + Ah*Bl^T + Al*Bh^T
// MODE 0: C = alpha * acc (fp32)
// MODE 1: t = acc + bias[col]; Oh/Ol = hi/lo bf16 split of t  (ld = ldc)
// CTA tile 128x256, BK=128, 256 threads (8 warps 2x4, warp tile 64x64).
// 2-stage cp.async pipeline; khalf-major smem (two 64-wide sub-tiles per
// stage), 128B rows, XOR-16B swizzle; fragment double-buffering over the
// 8 k16 sub-slices of each BK=128 tile.
// Requires M%128==0, N%256==0, K%128==0, 16B-aligned rows.
// ---------------------------------------------------------------------------
#define BM 128
#define BN 256
#define BK 128
#define A_HALF 16384                        // 128 rows * 128B
#define B_HALF 32768                        // 256 rows * 128B
#define A_BYTES (2 * A_HALF)                // 32768
#define B_BYTES (2 * B_HALF)                // 65536
#define STAGE_BYTES (A_BYTES + B_BYTES)     // 98304
#define NSTAGE 2
#define GEMM_SMEM (NSTAGE * STAGE_BYTES)    // 196608

template <int MODE>
__global__ __launch_bounds__(256, 1) void gemm_mma(
    const bf16* __restrict__ Ah, const bf16* __restrict__ Al,
    const bf16* __restrict__ Bh, const bf16* __restrict__ Bl,
    float* __restrict__ C, const float* __restrict__ bias,
    bf16* __restrict__ Oh, bf16* __restrict__ Ol,
    int K, int lda, int ldb, int ldc, float alpha,
    size_t sA, size_t sB, size_t sC)
{
    extern __shared__ char smem[];
    const uint32_t sbase = smem_u32(smem);

    const int tid = threadIdx.x;
    const int wid = tid >> 5;
    const int l   = tid & 31;
    const int m0 = blockIdx.x * BM;
    const int n0 = blockIdx.y * BN;
    const int z  = blockIdx.z;
    Ah += (size_t)z * sA; Al += (size_t)z * sA;
    Bh += (size_t)z * sB; Bl += (size_t)z * sB;

    const int NCP = K / BK;
    const int NT  = 3 * NCP;      // hi*hi, hi*lo, lo*hi

    const int wm = (wid >> 2) * 64;   // warp M offset
    const int wn = (wid & 3) * 64;    // warp N offset

    float acc[4][8][4];
#pragma unroll
    for (int i = 0; i < 4; i++)
#pragma unroll
        for (int j = 0; j < 8; j++)
#pragma unroll
            for (int t = 0; t < 4; t++) acc[i][j][t] = 0.0f;

    auto load_stage = [&](int s, int kt) {
        const int p  = kt / NCP;
        const int kc = (kt - p * NCP) * BK;
        const bf16* A = (p < 2) ? Ah : Al;
        const bf16* B = (p == 1) ? Bl : Bh;
        const uint32_t ast = sbase + s * STAGE_BYTES;
        const uint32_t bst = ast + A_BYTES;
        // A: 2 khalves x 128 rows x 8 chunks = 2048 16B chunks
#pragma unroll
        for (int h = 0; h < 8; h++) {
            const int c  = tid + h * 256;
            const int kh = c >> 10;
            const int rm = c & 1023;
            const int r  = rm >> 3, cc = rm & 7;
            const uint32_t da = ast + kh * A_HALF + r * 128 + ((cc * 16) ^ ((r & 7) * 16));
            const bf16* ga = A + (size_t)(m0 + r) * lda + kc + kh * 64 + cc * 8;
            asm volatile("cp.async.cg.shared.global [%0], [%1], 16;" :: "r"(da), "l"(ga));
        }
        // B: 2 khalves x 256 rows x 8 chunks = 4096 16B chunks
#pragma unroll
        for (int h = 0; h < 16; h++) {
            const int c  = tid + h * 256;
            const int kh = c >> 11;
            const int rm = c & 2047;
            const int r  = rm >> 3, cc = rm & 7;
            const uint32_t db = bst + kh * B_HALF + r * 128 + ((cc * 16) ^ ((r & 7) * 16));
            const bf16* gb = B + (size_t)(n0 + r) * ldb + kc + kh * 64 + cc * 8;
            asm volatile("cp.async.cg.shared.global [%0], [%1], 16;" :: "r"(db), "l"(gb));
        }
        asm volatile("cp.async.commit_group;" ::: "memory");
    };

    load_stage(0, 0);

    // per-lane ldmatrix address components (within a khalf)
    const uint32_t xorv = (l & 7) * 16;
    const int arow = wm + (l & 15);               // + 16*i
    const uint32_t acolb = (l >> 4) * 16;         // + 32*kk
    const int brow = wn + (l & 7) + (l >> 4) * 8; // + 16*j
    const uint32_t bcolb = ((l >> 3) & 1) * 16;   // + 32*kk

    for (int kt = 0; kt < NT; kt++) {
        const int cur = kt & 1;
        asm volatile("cp.async.wait_group 0;" ::: "memory");
        __syncthreads();
        if (kt + 1 < NT) load_stage(cur ^ 1, kt + 1);

        const uint32_t ast = sbase + cur * STAGE_BYTES;
        const uint32_t bst = ast + A_BYTES;

        // 8 k16 sub-slices (khalf = s8>>2, kk = s8&3), double-buffered frags
        uint32_t af[2][4][4], bfr[2][4][4];
#pragma unroll
        for (int i = 0; i < 4; i++)
            ldsm4(af[0][i], ast + (arow + 16 * i) * 128 + (acolb ^ xorv));
#pragma unroll
        for (int j = 0; j < 4; j++)
            ldsm4(bfr[0][j], bst + (brow + 16 * j) * 128 + (bcolb ^ xorv));

#pragma unroll
        for (int s8 = 0; s8 < 8; s8++) {
            const int cb = s8 & 1, nb = cb ^ 1;
            if (s8 < 7) {
                const int kh = (s8 + 1) >> 2, kk = (s8 + 1) & 3;
#pragma unroll
                for (int i = 0; i < 4; i++)
                    ldsm4(af[nb][i], ast + kh * A_HALF + (arow + 16 * i) * 128
                                         + ((acolb + 32 * kk) ^ xorv));
#pragma unroll
                for (int j = 0; j < 4; j++)
                    ldsm4(bfr[nb][j], bst + kh * B_HALF + (brow + 16 * j) * 128
                                          + ((bcolb + 32 * kk) ^ xorv));
            }
#pragma unroll
            for (int i = 0; i < 4; i++)
#pragma unroll
                for (int j = 0; j < 8; j++)
                    mma16816(acc[i][j], af[cb][i], &bfr[cb][j >> 1][(j & 1) * 2]);
        }
        // no trailing barrier: next iteration's top barrier protects the ring
    }

    // epilogue: c0,c1 -> (row, col..col+1); c2,c3 -> (row+8, ...)
    const int er = l >> 2, ec = (l & 3) * 2;
#pragma unroll
    for (int i = 0; i < 4; i++) {
        const int row = m0 + wm + 16 * i + er;
#pragma unroll
        for (int j = 0; j < 8; j++) {
            const int col = n0 + wn + 8 * j + ec;
            if (MODE == 0) {
                float* Cz = C + (size_t)z * sC;
                float2 v0 = {acc[i][j][0] * alpha, acc[i][j][1] * alpha};
                float2 v1 = {acc[i][j][2] * alpha, acc[i][j][3] * alpha};
                *(float2*)(Cz + (size_t)row * ldc + col) = v0;
                *(float2*)(Cz + (size_t)(row + 8) * ldc + col) = v1;
            } else {
                const float b0 = bias[col], b1 = bias[col + 1];
                float t00 = acc[i][j][0] + b0, t01 = acc[i][j][1] + b1;
                float t10 = acc[i][j][2] + b0, t11 = acc[i][j][3] + b1;
                bf16 h00 = __float2bfloat16(t00), h01 = __float2bfloat16(t01);
                bf16 h10 = __float2bfloat16(t10), h11 = __float2bfloat16(t11);
                float l00 = t00 - __bfloat162float(h00), l01 = t01 - __bfloat162float(h01);
                float l10 = t10 - __bfloat162float(h10), l11 = t11 - __bfloat162float(h11);
                uint32_t hp0, hp1;
                { __nv_bfloat162 t = {h00, h01}; hp0 = *(uint32_t*)&t; }
                { __nv_bfloat162 t = {h10, h11}; hp1 = *(uint32_t*)&t; }
                *(uint32_t*)(Oh + (size_t)row * ldc + col) = hp0;
                *(uint32_t*)(Oh + (size_t)(row + 8) * ldc + col) = hp1;
                *(uint32_t*)(Ol + (size_t)row * ldc + col) = pack_bf2(l00, l01);
                *(uint32_t*)(Ol + (size_t)(row + 8) * ldc + col) = pack_bf2(l10, l11);
            }
        }
    }
}

// ---------------- fused prep: split x + [Wq;Wk;Wv] hi/lo, concat bias ------
#define N_X4 (NTD / 4)                       // 3145728
#define N_W4 (WSZ / 4)                       // 147456
#define N_B4 (QKV / 4)                       // 576
#define PREP_TOT (N_X4 + 3 * N_W4 + N_B4)

__global__ __launch_bounds__(256) void prep_k(
    const float* __restrict__ x,
    const float* __restrict__ Wq, const float* __restrict__ Wk, const float* __restrict__ Wv,
    const float* __restrict__ bq, const float* __restrict__ bk, const float* __restrict__ bv,
    bf16* __restrict__ xh, bf16* __restrict__ xl,
    bf16* __restrict__ wch, bf16* __restrict__ wcl,
    float* __restrict__ bias)
{
    size_t i = (size_t)blockIdx.x * 256 + threadIdx.x;
    if (i >= PREP_TOT) return;

    if (i >= (size_t)N_X4 + 3 * N_W4) {      // bias concat region
        const int j = (int)(i - ((size_t)N_X4 + 3 * N_W4)) * 4;
        float4 o;
        float* po = (float*)&o;
#pragma unroll
        for (int e = 0; e < 4; e++) {
            const int c = j + e;
            po[e] = (c < DIM) ? bq[c] : (c < 2 * DIM) ? bk[c - DIM] : bv[c - 2 * DIM];
        }
        *(float4*)(bias + j) = o;
        return;
    }

    const float* src;
    size_t off;
    bf16 *dh, *dl;
    if (i < N_X4) { src = x; off = i; dh = xh; dl = xl; }
    else {
        size_t r = i - N_X4;
        const int w = (int)(r / N_W4);
        off = r - (size_t)w * N_W4;
        src = (w == 0) ? Wq : (w == 1) ? Wk : Wv;
        dh = wch + (size_t)w * WSZ; dl = wcl + (size_t)w * WSZ;
    }
    float4 v = ((const float4*)src)[off];
    float vv[4] = {v.x, v.y, v.z, v.w};
    union { unsigned short u[4]; uint2 q; } hh, ll;
#pragma unroll
    for (int e = 0; e < 4; e++) {
        bf16 hb = __float2bfloat16(vv[e]);
        bf16 lb = __float2bfloat16(vv[e] - __bfloat162float(hb));
        hh.u[e] = *(unsigned short*)&hb;
        ll.u[e] = *(unsigned short*)&lb;
    }
    ((uint2*)dh)[off] = hh.q;
    ((uint2*)dl)[off] = ll.q;
}

// ---------------- transpose V[b][s][d](ldin) -> Vt[b][d][s] (hi & lo) ------
__global__ void transpose_k(const bf16* __restrict__ vh, const bf16* __restrict__ vl,
                            bf16* __restrict__ th, bf16* __restrict__ tl, int ldin)
{
    __shared__ bf16 sh[32][33], sl[32][33];
    const int z = blockIdx.z;
    const size_t ibi = (size_t)z * SEQ * ldin;
    const size_t ibo = (size_t)z * SEQ * DIM;
    const int d0 = blockIdx.x * 32, s0 = blockIdx.y * 32;
    const int tx = threadIdx.x, ty = threadIdx.y;
#pragma unroll
    for (int i = 0; i < 32; i += 8) {
        sh[ty + i][tx] = vh[ibi + (size_t)(s0 + ty + i) * ldin + d0 + tx];
        sl[ty + i][tx] = vl[ibi + (size_t)(s0 + ty + i) * ldin + d0 + tx];
    }
    __syncthreads();
#pragma unroll
    for (int i = 0; i < 32; i += 8) {
        th[ibo + (size_t)(d0 + ty + i) * SEQ + s0 + tx] = sh[tx][ty + i];
        tl[ibo + (size_t)(d0 + ty + i) * SEQ + s0 + tx] = sl[tx][ty + i];
    }
}

// ---------------- softmax: fp32 scores row -> P hi/lo bf16 ----------------
__global__ __launch_bounds__(256) void softmax_k(const float* __restrict__ S,
                                                 bf16* __restrict__ ph, bf16* __restrict__ pl)
{
    const size_t rb = (size_t)blockIdx.x * SEQ;
    const float* p = S + rb;
    const int tid = threadIdx.x;

    float4 v[4];
#pragma unroll
    for (int i = 0; i < 4; i++) v[i] = *(const float4*)(p + tid * 4 + i * 1024);

    float m = -INFINITY;
#pragma unroll
    for (int i = 0; i < 4; i++)
        m = fmaxf(m, fmaxf(fmaxf(v[i].x, v[i].y), fmaxf(v[i].z, v[i].w)));

    __shared__ float red[256];
    red[tid] = m; __syncthreads();
#pragma unroll
    for (int s = 128; s > 0; s >>= 1) {
        if (tid < s) red[tid] = fmaxf(red[tid], red[tid + s]);
        __syncthreads();
    }
    m = red[0]; __syncthreads();

    float sum = 0.0f;
#pragma unroll
    for (int i = 0; i < 4; i++) {
        v[i].x = fexp(v[i].x - m); v[i].y = fexp(v[i].y - m);
        v[i].z = fexp(v[i].z - m); v[i].w = fexp(v[i].w - m);
        sum += v[i].x + v[i].y + v[i].z + v[i].w;
    }
    red[tid] = sum; __syncthreads();
#pragma unroll
    for (int s = 128; s > 0; s >>= 1) {
        if (tid < s) red[tid] += red[tid + s];
        __syncthreads();
    }
    const float inv = 1.0f / red[0];

#pragma unroll
    for (int i = 0; i < 4; i++) {
        float vv[4] = {v[i].x * inv, v[i].y * inv, v[i].z * inv, v[i].w * inv};
        union { unsigned short u[4]; uint2 q; } hh, ll;
#pragma unroll
        for (int e = 0; e < 4; e++) {
            bf16 hb = __float2bfloat16(vv[e]);
            bf16 lb = __float2bfloat16(vv[e] - __bfloat162float(hb));
            hh.u[e] = *(unsigned short*)&hb;
            ll.u[e] = *(unsigned short*)&lb;
        }
        *(uint2*)(ph + rb + tid * 4 + i * 1024) = hh.q;
        *(uint2*)(pl + rb + tid * 4 + i * 1024) = ll.q;
    }
}

// ---------------- launch ----------------
extern "C" void kernel_launch(void* const* d_in, const int* in_sizes, int n_in,
                              void* d_out, int out_size)
{
    const float* x  = (const float*)d_in[0];
    const float* Wq = (const float*)d_in[1];
    const float* bq = (const float*)d_in[2];
    const float* Wk = (const float*)d_in[3];
    const float* bk = (const float*)d_in[4];
    const float* Wv = (const float*)d_in[5];
    const float* bv = (const float*)d_in[6];
    float* out = (float*)d_out;

    bf16 *xh, *xl, *wch, *wcl, *qkvh, *qkvl, *vth, *vtl, *pph, *ppl;
    float *sc, *bias;
    cudaGetSymbolAddress((void**)&xh, g_xh);     cudaGetSymbolAddress((void**)&xl, g_xl);
    cudaGetSymbolAddress((void**)&wch, g_wch);   cudaGetSymbolAddress((void**)&wcl, g_wcl);
    cudaGetSymbolAddress((void**)&qkvh, g_qkvh); cudaGetSymbolAddress((void**)&qkvl, g_qkvl);
    cudaGetSymbolAddress((void**)&vth, g_vth);   cudaGetSymbolAddress((void**)&vtl, g_vtl);
    cudaGetSymbolAddress((void**)&pph, g_ph);    cudaGetSymbolAddress((void**)&ppl, g_pl);
    cudaGetSymbolAddress((void**)&sc, g_s);      cudaGetSymbolAddress((void**)&bias, g_bias);

    cudaFuncSetAttribute(gemm_mma<0>, cudaFuncAttributeMaxDynamicSharedMemorySize, GEMM_SMEM);
    cudaFuncSetAttribute(gemm_mma<1>, cudaFuncAttributeMaxDynamicSharedMemorySize, GEMM_SMEM);

    const float scale = 1.0f / sqrtf((float)DIM);

    // 1. fused prep: hi/lo splits + bias concat (single launch)
    prep_k<<<(int)((PREP_TOT + 255) / 256), 256>>>(
        x, Wq, Wk, Wv, bq, bk, bv, xh, xl, wch, wcl, bias);

    // 2. fused QKV projection: [16384, 2304] = X * Wc^T + bias  (hi/lo epilogue)
    gemm_mma<1><<<dim3(NTOK / BM, QKV / BN, 1), 256, GEMM_SMEM>>>(
        xh, xl, wch, wcl, nullptr, bias, qkvh, qkvl,
        DIM, DIM, DIM, QKV, 1.0f, 0, 0, 0);

    // 3. transpose V (qkv columns 1536..2303) -> Vt[b][d][s]
    transpose_k<<<dim3(DIM / 32, SEQ / 32, BATCH), dim3(32, 8)>>>(
        qkvh + 2 * DIM, qkvl + 2 * DIM, vth, vtl, QKV);

    // 4. scores[b] = scale * Q[b] K[b]^T   (q, k are qkv slices, ld = 2304)
    gemm_mma<0><<<dim3(SEQ / BM, SEQ / BN, BATCH), 256, GEMM_SMEM>>>(
        qkvh, qkvl, qkvh + DIM, qkvl + DIM, sc, nullptr, nullptr, nullptr,
        DIM, QKV, QKV, SEQ, scale,
        (size_t)SEQ * QKV, (size_t)SEQ * QKV, (size_t)SEQ * SEQ);

    // 5. softmax rows -> P hi/lo
    softmax_k<<<NTOK, 256>>>(sc, pph, ppl);

    // 6. out[b] = P[b] V[b]   (B operand = Vt, K-major over seq)
    gemm_mma<0><<<dim3(SEQ / BM, DIM / BN, BATCH), 256, GEMM_SMEM>>>(
        pph, ppl, vth, vtl, out, nullptr, nullptr, nullptr,
        SEQ, SEQ, SEQ, DIM, 1.0f,
        (size_t)SEQ * SEQ, (size_t)SEQ * DIM, (size_t)SEQ * DIM);

    (void)in_sizes; (void)n_in; (void)out_size;
}

// round 15
// speedup vs baseline: 1.4511x; 1.3147x over previous
#include <cuda_runtime.h>
#include <cuda_fp16.h>
#include <cstdint>
#include <math.h>

using hf = __half;

#define BATCH 4
#define SEQ   4096
#define DIM   768
#define QKV   (3 * DIM)                     // 2304
#define NTOK  (BATCH * SEQ)                 // 16384
#define NTD   ((size_t)NTOK * DIM)
#define NTQ   ((size_t)NTOK * QKV)
#define WSZ   ((size_t)DIM * DIM)
#define SSZ   ((size_t)BATCH * SEQ * SEQ)

// ---------------- device scratch (allocation-free rule) ----------------
__device__ hf    g_xh[NTD], g_xl[NTD];
__device__ hf    g_wch[3 * WSZ], g_wcl[3 * WSZ];   // [Wq;Wk;Wv] hi/lo
__device__ float g_bias[QKV];
__device__ hf    g_qkvh[NTQ], g_qkvl[NTQ];         // fused q|k|v, ld = 2304
__device__ hf    g_vth[NTD];                       // V transposed (hi only)
__device__ float g_s[SSZ];                         // scores fp32
__device__ hf    g_ph[SSZ], g_pl[SSZ];             // softmax 1024*P hi/lo

__device__ __forceinline__ uint32_t smem_u32(const void* p) {
    uint32_t a;
    asm("{ .reg .u64 t; cvta.to.shared.u64 t, %1; cvt.u32.u64 %0, t; }" : "=r"(a) : "l"(p));
    return a;
}

__device__ __forceinline__ void ldsm4(uint32_t* r, uint32_t addr) {
    asm volatile("ldmatrix.sync.aligned.m8n8.x4.shared.b16 {%0,%1,%2,%3}, [%4];"
                 : "=r"(r[0]), "=r"(r[1]), "=r"(r[2]), "=r"(r[3]) : "r"(addr));
}
__device__ __forceinline__ void mma16816(float* d, const uint32_t* a, const uint32_t* b) {
    asm volatile("mma.sync.aligned.m16n8k16.row.col.f32.f16.f16.f32 "
                 "{%0,%1,%2,%3}, {%4,%5,%6,%7}, {%8,%9}, {%0,%1,%2,%3};"
                 : "+f"(d[0]), "+f"(d[1]), "+f"(d[2]), "+f"(d[3])
                 : "r"(a[0]), "r"(a[1]), "r"(a[2]), "r"(a[3]), "r"(b[0]), "r"(b[1]));
}

__device__ __forceinline__ uint32_t pack_h2(float a, float b) {
    __half2 t = __floats2half2_rn(a, b);
    return *(uint32_t*)&t;
}

// Fast exp on the FMA pipe. |err| ~ 5e-9 over the used range. x <= 0 here.
__device__ __forceinline__ float fexp(float x) {
    x = fmaxf(x, -80.0f);
    float n = rintf(x * 1.4426950408889634f);
    float t = fmaf(n, -0.6931471805599453f, x);
    float p = 1.9841270e-4f;
    p = fmaf(p, t, 1.3888889e-3f);
    p = fmaf(p, t, 8.3333333e-3f);
    p = fmaf(p, t, 4.1666667e-2f);
    p = fmaf(p, t, 1.6666667e-1f);
    p = fmaf(p, t, 0.5f);
    p = fmaf(p, t, 1.0f);
    p = fmaf(p, t, 1.0f);
    float s = __int_as_float(((int)n + 127) << 23);
    return p * s;
}

// ---------------------------------------------------------------------------
// NT GEMM via raw mma.sync(f16) + ldmatrix, multi-pass hi/lo split:
//   NPASS=2: acc = Ah*Bh^T + Al*Bh^T            (A exact, B single fp16)
//   NPASS=3: acc = Ah*Bh^T + Al*Bh^T + Ah*Bl^T  (both sides ~22-bit)
// MODE 0: C = alpha * acc (fp32)
// MODE 1: t = acc + bias[col]; Oh/Ol = fp16 hi/lo split of t  (ld = ldc)
// CTA tile 128x256, BK=128, 256 threads (8 warps 2x4, warp tile 64x64).
// 2-stage cp.async pipeline; khalf-major smem, 128B rows, XOR-16B swizzle;
// fragment double-buffering over the 8 k16 sub-slices per BK tile.
// Requires M%128==0, N%256==0, K%128==0, 16B-aligned rows.
// ---------------------------------------------------------------------------
#define BM 128
#define BN 256
#define BK 128
#define A_HALF 16384
#define B_HALF 32768
#define A_BYTES (2 * A_HALF)
#define B_BYTES (2 * B_HALF)
#define STAGE_BYTES (A_BYTES + B_BYTES)     // 98304
#define GEMM_SMEM (2 * STAGE_BYTES)         // 196608

template <int MODE, int NPASS>
__global__ __launch_bounds__(256, 1) void gemm_mma(
    const hf* __restrict__ Ah, const hf* __restrict__ Al,
    const hf* __restrict__ Bh, const hf* __restrict__ Bl,
    float* __restrict__ C, const float* __restrict__ bias,
    hf* __restrict__ Oh, hf* __restrict__ Ol,
    int K, int lda, int ldb, int ldc, float alpha,
    size_t sA, size_t sB, size_t sC)
{
    extern __shared__ char smem[];
    const uint32_t sbase = smem_u32(smem);

    const int tid = threadIdx.x;
    const int wid = tid >> 5;
    const int l   = tid & 31;
    const int m0 = blockIdx.x * BM;
    const int n0 = blockIdx.y * BN;
    const int z  = blockIdx.z;
    Ah += (size_t)z * sA; Al += (size_t)z * sA;
    Bh += (size_t)z * sB; Bl += (size_t)z * sB;

    const int NCP = K / BK;
    const int NT  = NPASS * NCP;

    const int wm = (wid >> 2) * 64;
    const int wn = (wid & 3) * 64;

    float acc[4][8][4];
#pragma unroll
    for (int i = 0; i < 4; i++)
#pragma unroll
        for (int j = 0; j < 8; j++)
#pragma unroll
            for (int t = 0; t < 4; t++) acc[i][j][t] = 0.0f;

    auto load_stage = [&](int s, int kt) {
        const int p  = kt / NCP;
        const int kc = (kt - p * NCP) * BK;
        const hf* A = (p == 1) ? Al : Ah;          // p0:AhBh  p1:AlBh  p2:AhBl
        const hf* B = (p == 2) ? Bl : Bh;
        const uint32_t ast = sbase + s * STAGE_BYTES;
        const uint32_t bst = ast + A_BYTES;
#pragma unroll
        for (int h = 0; h < 8; h++) {              // A: 2048 16B chunks
            const int c  = tid + h * 256;
            const int kh = c >> 10;
            const int rm = c & 1023;
            const int r  = rm >> 3, cc = rm & 7;
            const uint32_t da = ast + kh * A_HALF + r * 128 + ((cc * 16) ^ ((r & 7) * 16));
            const hf* ga = A + (size_t)(m0 + r) * lda + kc + kh * 64 + cc * 8;
            asm volatile("cp.async.cg.shared.global [%0], [%1], 16;" :: "r"(da), "l"(ga));
        }
#pragma unroll
        for (int h = 0; h < 16; h++) {             // B: 4096 16B chunks
            const int c  = tid + h * 256;
            const int kh = c >> 11;
            const int rm = c & 2047;
            const int r  = rm >> 3, cc = rm & 7;
            const uint32_t db = bst + kh * B_HALF + r * 128 + ((cc * 16) ^ ((r & 7) * 16));
            const hf* gb = B + (size_t)(n0 + r) * ldb + kc + kh * 64 + cc * 8;
            asm volatile("cp.async.cg.shared.global [%0], [%1], 16;" :: "r"(db), "l"(gb));
        }
        asm volatile("cp.async.commit_group;" ::: "memory");
    };

    load_stage(0, 0);

    const uint32_t xorv = (l & 7) * 16;
    const int arow = wm + (l & 15);
    const uint32_t acolb = (l >> 4) * 16;
    const int brow = wn + (l & 7) + (l >> 4) * 8;
    const uint32_t bcolb = ((l >> 3) & 1) * 16;

    for (int kt = 0; kt < NT; kt++) {
        const int cur = kt & 1;
        asm volatile("cp.async.wait_group 0;" ::: "memory");
        __syncthreads();
        if (kt + 1 < NT) load_stage(cur ^ 1, kt + 1);

        const uint32_t ast = sbase + cur * STAGE_BYTES;
        const uint32_t bst = ast + A_BYTES;

        uint32_t af[2][4][4], bfr[2][4][4];
#pragma unroll
        for (int i = 0; i < 4; i++)
            ldsm4(af[0][i], ast + (arow + 16 * i) * 128 + (acolb ^ xorv));
#pragma unroll
        for (int j = 0; j < 4; j++)
            ldsm4(bfr[0][j], bst + (brow + 16 * j) * 128 + (bcolb ^ xorv));

#pragma unroll
        for (int s8 = 0; s8 < 8; s8++) {
            const int cb = s8 & 1, nb = cb ^ 1;
            if (s8 < 7) {
                const int kh = (s8 + 1) >> 2, kk = (s8 + 1) & 3;
#pragma unroll
                for (int i = 0; i < 4; i++)
                    ldsm4(af[nb][i], ast + kh * A_HALF + (arow + 16 * i) * 128
                                         + ((acolb + 32 * kk) ^ xorv));
#pragma unroll
                for (int j = 0; j < 4; j++)
                    ldsm4(bfr[nb][j], bst + kh * B_HALF + (brow + 16 * j) * 128
                                          + ((bcolb + 32 * kk) ^ xorv));
            }
#pragma unroll
            for (int i = 0; i < 4; i++)
#pragma unroll
                for (int j = 0; j < 8; j++)
                    mma16816(acc[i][j], af[cb][i], &bfr[cb][j >> 1][(j & 1) * 2]);
        }
    }

    const int er = l >> 2, ec = (l & 3) * 2;
#pragma unroll
    for (int i = 0; i < 4; i++) {
        const int row = m0 + wm + 16 * i + er;
#pragma unroll
        for (int j = 0; j < 8; j++) {
            const int col = n0 + wn + 8 * j + ec;
            if (MODE == 0) {
                float* Cz = C + (size_t)z * sC;
                float2 v0 = {acc[i][j][0] * alpha, acc[i][j][1] * alpha};
                float2 v1 = {acc[i][j][2] * alpha, acc[i][j][3] * alpha};
                *(float2*)(Cz + (size_t)row * ldc + col) = v0;
                *(float2*)(Cz + (size_t)(row + 8) * ldc + col) = v1;
            } else {
                const float b0 = bias[col], b1 = bias[col + 1];
                float t00 = acc[i][j][0] + b0, t01 = acc[i][j][1] + b1;
                float t10 = acc[i][j][2] + b0, t11 = acc[i][j][3] + b1;
                hf h00 = __float2half(t00), h01 = __float2half(t01);
                hf h10 = __float2half(t10), h11 = __float2half(t11);
                float l00 = t00 - __half2float(h00), l01 = t01 - __half2float(h01);
                float l10 = t10 - __half2float(h10), l11 = t11 - __half2float(h11);
                uint32_t hp0, hp1;
                { __half2 t = {h00, h01}; hp0 = *(uint32_t*)&t; }
                { __half2 t = {h10, h11}; hp1 = *(uint32_t*)&t; }
                *(uint32_t*)(Oh + (size_t)row * ldc + col) = hp0;
                *(uint32_t*)(Oh + (size_t)(row + 8) * ldc + col) = hp1;
                *(uint32_t*)(Ol + (size_t)row * ldc + col) = pack_h2(l00, l01);
                *(uint32_t*)(Ol + (size_t)(row + 8) * ldc + col) = pack_h2(l10, l11);
            }
        }
    }
}

// ---------------- fused prep: split x + [Wq;Wk;Wv] hi/lo, concat bias ------
#define N_X4 (NTD / 4)
#define N_W4 (WSZ / 4)
#define N_B4 (QKV / 4)
#define PREP_TOT (N_X4 + 3 * N_W4 + N_B4)

__global__ __launch_bounds__(256) void prep_k(
    const float* __restrict__ x,
    const float* __restrict__ Wq, const float* __restrict__ Wk, const float* __restrict__ Wv,
    const float* __restrict__ bq, const float* __restrict__ bk, const float* __restrict__ bv,
    hf* __restrict__ xh, hf* __restrict__ xl,
    hf* __restrict__ wch, hf* __restrict__ wcl,
    float* __restrict__ bias)
{
    size_t i = (size_t)blockIdx.x * 256 + threadIdx.x;
    if (i >= PREP_TOT) return;

    if (i >= (size_t)N_X4 + 3 * N_W4) {
        const int j = (int)(i - ((size_t)N_X4 + 3 * N_W4)) * 4;
        float4 o;
        float* po = (float*)&o;
#pragma unroll
        for (int e = 0; e < 4; e++) {
            const int c = j + e;
            po[e] = (c < DIM) ? bq[c] : (c < 2 * DIM) ? bk[c - DIM] : bv[c - 2 * DIM];
        }
        *(float4*)(bias + j) = o;
        return;
    }

    const float* src;
    size_t off;
    hf *dh, *dl;
    if (i < N_X4) { src = x; off = i; dh = xh; dl = xl; }
    else {
        size_t r = i - N_X4;
        const int w = (int)(r / N_W4);
        off = r - (size_t)w * N_W4;
        src = (w == 0) ? Wq : (w == 1) ? Wk : Wv;
        dh = wch + (size_t)w * WSZ; dl = wcl + (size_t)w * WSZ;
    }
    float4 v = ((const float4*)src)[off];
    float vv[4] = {v.x, v.y, v.z, v.w};
    union { unsigned short u[4]; uint2 q; } hh, ll;
#pragma unroll
    for (int e = 0; e < 4; e++) {
        hf hb = __float2half(vv[e]);
        hf lb = __float2half(vv[e] - __half2float(hb));
        hh.u[e] = *(unsigned short*)&hb;
        ll.u[e] = *(unsigned short*)&lb;
    }
    ((uint2*)dh)[off] = hh.q;
    ((uint2*)dl)[off] = ll.q;
}

// ---------------- transpose Vh[b][s][d](ldin) -> Vt[b][d][s] ----------------
__global__ void transpose_k(const hf* __restrict__ vh, hf* __restrict__ th, int ldin)
{
    __shared__ hf sh[32][33];
    const int z = blockIdx.z;
    const size_t ibi = (size_t)z * SEQ * ldin;
    const size_t ibo = (size_t)z * SEQ * DIM;
    const int d0 = blockIdx.x * 32, s0 = blockIdx.y * 32;
    const int tx = threadIdx.x, ty = threadIdx.y;
#pragma unroll
    for (int i = 0; i < 32; i += 8)
        sh[ty + i][tx] = vh[ibi + (size_t)(s0 + ty + i) * ldin + d0 + tx];
    __syncthreads();
#pragma unroll
    for (int i = 0; i < 32; i += 8)
        th[ibo + (size_t)(d0 + ty + i) * SEQ + s0 + tx] = sh[tx][ty + i];
}

// ---------------- softmax: fp32 scores row -> (1024*P) hi/lo fp16 ----------
__global__ __launch_bounds__(256) void softmax_k(const float* __restrict__ S,
                                                 hf* __restrict__ ph, hf* __restrict__ pl)
{
    const size_t rb = (size_t)blockIdx.x * SEQ;
    const float* p = S + rb;
    const int tid = threadIdx.x;

    float4 v[4];
#pragma unroll
    for (int i = 0; i < 4; i++) v[i] = *(const float4*)(p + tid * 4 + i * 1024);

    float m = -INFINITY;
#pragma unroll
    for (int i = 0; i < 4; i++)
        m = fmaxf(m, fmaxf(fmaxf(v[i].x, v[i].y), fmaxf(v[i].z, v[i].w)));

    __shared__ float red[256];
    red[tid] = m; __syncthreads();
#pragma unroll
    for (int s = 128; s > 0; s >>= 1) {
        if (tid < s) red[tid] = fmaxf(red[tid], red[tid + s]);
        __syncthreads();
    }
    m = red[0]; __syncthreads();

    float sum = 0.0f;
#pragma unroll
    for (int i = 0; i < 4; i++) {
        v[i].x = fexp(v[i].x - m); v[i].y = fexp(v[i].y - m);
        v[i].z = fexp(v[i].z - m); v[i].w = fexp(v[i].w - m);
        sum += v[i].x + v[i].y + v[i].z + v[i].w;
    }
    red[tid] = sum; __syncthreads();
#pragma unroll
    for (int s = 128; s > 0; s >>= 1) {
        if (tid < s) red[tid] += red[tid + s];
        __syncthreads();
    }
    const float inv = 1024.0f / red[0];        // scaled: keeps fp16 lo normal

#pragma unroll
    for (int i = 0; i < 4; i++) {
        float vv[4] = {v[i].x * inv, v[i].y * inv, v[i].z * inv, v[i].w * inv};
        union { unsigned short u[4]; uint2 q; } hh, ll;
#pragma unroll
        for (int e = 0; e < 4; e++) {
            hf hb = __float2half(vv[e]);
            hf lb = __float2half(vv[e] - __half2float(hb));
            hh.u[e] = *(unsigned short*)&hb;
            ll.u[e] = *(unsigned short*)&lb;
        }
        *(uint2*)(ph + rb + tid * 4 + i * 1024) = hh.q;
        *(uint2*)(pl + rb + tid * 4 + i * 1024) = ll.q;
    }
}

// ---------------- launch ----------------
extern "C" void kernel_launch(void* const* d_in, const int* in_sizes, int n_in,
                              void* d_out, int out_size)
{
    const float* x  = (const float*)d_in[0];
    const float* Wq = (const float*)d_in[1];
    const float* bq = (const float*)d_in[2];
    const float* Wk = (const float*)d_in[3];
    const float* bk = (const float*)d_in[4];
    const float* Wv = (const float*)d_in[5];
    const float* bv = (const float*)d_in[6];
    float* out = (float*)d_out;

    hf *xh, *xl, *wch, *wcl, *qkvh, *qkvl, *vth, *pph, *ppl;
    float *sc, *bias;
    cudaGetSymbolAddress((void**)&xh, g_xh);     cudaGetSymbolAddress((void**)&xl, g_xl);
    cudaGetSymbolAddress((void**)&wch, g_wch);   cudaGetSymbolAddress((void**)&wcl, g_wcl);
    cudaGetSymbolAddress((void**)&qkvh, g_qkvh); cudaGetSymbolAddress((void**)&qkvl, g_qkvl);
    cudaGetSymbolAddress((void**)&vth, g_vth);
    cudaGetSymbolAddress((void**)&pph, g_ph);    cudaGetSymbolAddress((void**)&ppl, g_pl);
    cudaGetSymbolAddress((void**)&sc, g_s);      cudaGetSymbolAddress((void**)&bias, g_bias);

    cudaFuncSetAttribute((void*)gemm_mma<0, 2>, cudaFuncAttributeMaxDynamicSharedMemorySize, GEMM_SMEM);
    cudaFuncSetAttribute((void*)gemm_mma<1, 3>, cudaFuncAttributeMaxDynamicSharedMemorySize, GEMM_SMEM);

    const float scale = 1.0f / sqrtf((float)DIM);

    // 1. fused prep: fp16 hi/lo splits + bias concat
    prep_k<<<(int)((PREP_TOT + 255) / 256), 256>>>(
        x, Wq, Wk, Wv, bq, bk, bv, xh, xl, wch, wcl, bias);

    // 2. fused QKV projection (3-pass, ~exact): [16384,2304] = X*Wc^T + bias
    gemm_mma<1, 3><<<dim3(NTOK / BM, QKV / BN, 1), 256, GEMM_SMEM>>>(
        xh, xl, wch, wcl, nullptr, bias, qkvh, qkvl,
        DIM, DIM, DIM, QKV, 1.0f, 0, 0, 0);

    // 3. transpose V hi (qkv cols 1536..2303) -> Vt[b][d][s]
    transpose_k<<<dim3(DIM / 32, SEQ / 32, BATCH), dim3(32, 8)>>>(
        qkvh + 2 * DIM, vth, QKV);

    // 4. scores[b] = scale * Q[b] K[b]^T   (2-pass: Q exact, K single fp16)
    gemm_mma<0, 2><<<dim3(SEQ / BM, SEQ / BN, BATCH), 256, GEMM_SMEM>>>(
        qkvh, qkvl, qkvh + DIM, qkvh + DIM, sc, nullptr, nullptr, nullptr,
        DIM, QKV, QKV, SEQ, scale,
        (size_t)SEQ * QKV, (size_t)SEQ * QKV, (size_t)SEQ * SEQ);

    // 5. softmax rows -> (1024*P) hi/lo
    softmax_k<<<NTOK, 256>>>(sc, pph, ppl);

    // 6. out[b] = (1/1024) * P[b] V[b]   (2-pass: P exact, Vt single fp16)
    gemm_mma<0, 2><<<dim3(SEQ / BM, DIM / BN, BATCH), 256, GEMM_SMEM>>>(
        pph, ppl, vth, vth, out, nullptr, nullptr, nullptr,
        SEQ, SEQ, SEQ, DIM, 1.0f / 1024.0f,
        (size_t)SEQ * SEQ, (size_t)SEQ * DIM, (size_t)SEQ * DIM);

    (void)in_sizes; (void)n_in; (void)out_size;
}

// round 16
// speedup vs baseline: 1.7541x; 1.2088x over previous
#include <cuda_runtime.h>
#include <cuda_fp16.h>
#include <cstdint>
#include <math.h>

using hf = __half;

#define BATCH 4
#define SEQ   4096
#define DIM   768
#define QKV   (3 * DIM)                     // 2304
#define NTOK  (BATCH * SEQ)                 // 16384
#define NTD   ((size_t)NTOK * DIM)
#define NTQ   ((size_t)NTOK * QKV)
#define WSZ   ((size_t)DIM * DIM)
#define SSZ   ((size_t)BATCH * SEQ * SEQ)

// ---------------- device scratch (allocation-free rule) ----------------
__device__ hf    g_xh[NTD], g_xl[NTD];
__device__ hf    g_wch[3 * WSZ], g_wcl[3 * WSZ];   // [Wq;Wk;Wv] hi/lo
__device__ float g_bias[QKV];
__device__ hf    g_qkvh[NTQ], g_qkvl[NTQ];         // fused q|k|v, ld = 2304
__device__ hf    g_vth[NTD];                       // V transposed (hi only)
__device__ float g_s[SSZ];                         // scores fp32
__device__ hf    g_ph[SSZ];                        // softmax 1024*P (fp16)

__device__ __forceinline__ uint32_t smem_u32(const void* p) {
    uint32_t a;
    asm("{ .reg .u64 t; cvta.to.shared.u64 t, %1; cvt.u32.u64 %0, t; }" : "=r"(a) : "l"(p));
    return a;
}

__device__ __forceinline__ void ldsm4(uint32_t* r, uint32_t addr) {
    asm volatile("ldmatrix.sync.aligned.m8n8.x4.shared.b16 {%0,%1,%2,%3}, [%4];"
                 : "=r"(r[0]), "=r"(r[1]), "=r"(r[2]), "=r"(r[3]) : "r"(addr));
}
__device__ __forceinline__ void mma16816(float* d, const uint32_t* a, const uint32_t* b) {
    asm volatile("mma.sync.aligned.m16n8k16.row.col.f32.f16.f16.f32 "
                 "{%0,%1,%2,%3}, {%4,%5,%6,%7}, {%8,%9}, {%0,%1,%2,%3};"
                 : "+f"(d[0]), "+f"(d[1]), "+f"(d[2]), "+f"(d[3])
                 : "r"(a[0]), "r"(a[1]), "r"(a[2]), "r"(a[3]), "r"(b[0]), "r"(b[1]));
}

__device__ __forceinline__ uint32_t pack_h2(float a, float b) {
    __half2 t = __floats2half2_rn(a, b);
    return *(uint32_t*)&t;
}

// Fast exp on the FMA pipe. |err| ~ 5e-9 over the used range. x <= 0 here.
__device__ __forceinline__ float fexp(float x) {
    x = fmaxf(x, -80.0f);
    float n = rintf(x * 1.4426950408889634f);
    float t = fmaf(n, -0.6931471805599453f, x);
    float p = 1.9841270e-4f;
    p = fmaf(p, t, 1.3888889e-3f);
    p = fmaf(p, t, 8.3333333e-3f);
    p = fmaf(p, t, 4.1666667e-2f);
    p = fmaf(p, t, 1.6666667e-1f);
    p = fmaf(p, t, 0.5f);
    p = fmaf(p, t, 1.0f);
    p = fmaf(p, t, 1.0f);
    float s = __int_as_float(((int)n + 127) << 23);
    return p * s;
}

// ---------------------------------------------------------------------------
// NT GEMM via raw mma.sync(f16) + ldmatrix, multi-pass hi/lo split:
//   NPASS=1: acc = Ah*Bh^T                      (single fp16 both sides)
//   NPASS=2: acc = Ah*Bh^T + Al*Bh^T            (A exact, B single fp16)
//   NPASS=3: acc = Ah*Bh^T + Al*Bh^T + Ah*Bl^T  (both sides ~22-bit)
// MODE 0: C = alpha * acc (fp32)
// MODE 1: t = acc + bias[col]; Oh/Ol = fp16 hi/lo split of t  (ld = ldc)
// CTA tile 128x256, BK=128, 256 threads (8 warps 2x4, warp tile 64x64).
// 2-stage cp.async pipeline; khalf-major smem, 128B rows, XOR-16B swizzle;
// fragment double-buffering over the 8 k16 sub-slices per BK tile.
// Requires M%128==0, N%256==0, K%128==0, 16B-aligned rows.
// ---------------------------------------------------------------------------
#define BM 128
#define BN 256
#define BK 128
#define A_HALF 16384
#define B_HALF 32768
#define A_BYTES (2 * A_HALF)
#define B_BYTES (2 * B_HALF)
#define STAGE_BYTES (A_BYTES + B_BYTES)     // 98304
#define GEMM_SMEM (2 * STAGE_BYTES)         // 196608

template <int MODE, int NPASS>
__global__ __launch_bounds__(256, 1) void gemm_mma(
    const hf* __restrict__ Ah, const hf* __restrict__ Al,
    const hf* __restrict__ Bh, const hf* __restrict__ Bl,
    float* __restrict__ C, const float* __restrict__ bias,
    hf* __restrict__ Oh, hf* __restrict__ Ol,
    int K, int lda, int ldb, int ldc, float alpha,
    size_t sA, size_t sB, size_t sC)
{
    extern __shared__ char smem[];
    const uint32_t sbase = smem_u32(smem);

    const int tid = threadIdx.x;
    const int wid = tid >> 5;
    const int l   = tid & 31;
    const int m0 = blockIdx.x * BM;
    const int n0 = blockIdx.y * BN;
    const int z  = blockIdx.z;
    Ah += (size_t)z * sA; Al += (size_t)z * sA;
    Bh += (size_t)z * sB; Bl += (size_t)z * sB;

    const int NCP = K / BK;
    const int NT  = NPASS * NCP;

    const int wm = (wid >> 2) * 64;
    const int wn = (wid & 3) * 64;

    float acc[4][8][4];
#pragma unroll
    for (int i = 0; i < 4; i++)
#pragma unroll
        for (int j = 0; j < 8; j++)
#pragma unroll
            for (int t = 0; t < 4; t++) acc[i][j][t] = 0.0f;

    auto load_stage = [&](int s, int kt) {
        const int p  = kt / NCP;
        const int kc = (kt - p * NCP) * BK;
        const hf* A = (p == 1) ? Al : Ah;          // p0:AhBh  p1:AlBh  p2:AhBl
        const hf* B = (p == 2) ? Bl : Bh;
        const uint32_t ast = sbase + s * STAGE_BYTES;
        const uint32_t bst = ast + A_BYTES;
#pragma unroll
        for (int h = 0; h < 8; h++) {              // A: 2048 16B chunks
            const int c  = tid + h * 256;
            const int kh = c >> 10;
            const int rm = c & 1023;
            const int r  = rm >> 3, cc = rm & 7;
            const uint32_t da = ast + kh * A_HALF + r * 128 + ((cc * 16) ^ ((r & 7) * 16));
            const hf* ga = A + (size_t)(m0 + r) * lda + kc + kh * 64 + cc * 8;
            asm volatile("cp.async.cg.shared.global [%0], [%1], 16;" :: "r"(da), "l"(ga));
        }
#pragma unroll
        for (int h = 0; h < 16; h++) {             // B: 4096 16B chunks
            const int c  = tid + h * 256;
            const int kh = c >> 11;
            const int rm = c & 2047;
            const int r  = rm >> 3, cc = rm & 7;
            const uint32_t db = bst + kh * B_HALF + r * 128 + ((cc * 16) ^ ((r & 7) * 16));
            const hf* gb = B + (size_t)(n0 + r) * ldb + kc + kh * 64 + cc * 8;
            asm volatile("cp.async.cg.shared.global [%0], [%1], 16;" :: "r"(db), "l"(gb));
        }
        asm volatile("cp.async.commit_group;" ::: "memory");
    };

    load_stage(0, 0);

    const uint32_t xorv = (l & 7) * 16;
    const int arow = wm + (l & 15);
    const uint32_t acolb = (l >> 4) * 16;
    const int brow = wn + (l & 7) + (l >> 4) * 8;
    const uint32_t bcolb = ((l >> 3) & 1) * 16;

    for (int kt = 0; kt < NT; kt++) {
        const int cur = kt & 1;
        asm volatile("cp.async.wait_group 0;" ::: "memory");
        __syncthreads();
        if (kt + 1 < NT) load_stage(cur ^ 1, kt + 1);

        const uint32_t ast = sbase + cur * STAGE_BYTES;
        const uint32_t bst = ast + A_BYTES;

        uint32_t af[2][4][4], bfr[2][4][4];
#pragma unroll
        for (int i = 0; i < 4; i++)
            ldsm4(af[0][i], ast + (arow + 16 * i) * 128 + (acolb ^ xorv));
#pragma unroll
        for (int j = 0; j < 4; j++)
            ldsm4(bfr[0][j], bst + (brow + 16 * j) * 128 + (bcolb ^ xorv));

#pragma unroll
        for (int s8 = 0; s8 < 8; s8++) {
            const int cb = s8 & 1, nb = cb ^ 1;
            if (s8 < 7) {
                const int kh = (s8 + 1) >> 2, kk = (s8 + 1) & 3;
#pragma unroll
                for (int i = 0; i < 4; i++)
                    ldsm4(af[nb][i], ast + kh * A_HALF + (arow + 16 * i) * 128
                                         + ((acolb + 32 * kk) ^ xorv));
#pragma unroll
                for (int j = 0; j < 4; j++)
                    ldsm4(bfr[nb][j], bst + kh * B_HALF + (brow + 16 * j) * 128
                                          + ((bcolb + 32 * kk) ^ xorv));
            }
#pragma unroll
            for (int i = 0; i < 4; i++)
#pragma unroll
                for (int j = 0; j < 8; j++)
                    mma16816(acc[i][j], af[cb][i], &bfr[cb][j >> 1][(j & 1) * 2]);
        }
    }

    const int er = l >> 2, ec = (l & 3) * 2;
#pragma unroll
    for (int i = 0; i < 4; i++) {
        const int row = m0 + wm + 16 * i + er;
#pragma unroll
        for (int j = 0; j < 8; j++) {
            const int col = n0 + wn + 8 * j + ec;
            if (MODE == 0) {
                float* Cz = C + (size_t)z * sC;
                float2 v0 = {acc[i][j][0] * alpha, acc[i][j][1] * alpha};
                float2 v1 = {acc[i][j][2] * alpha, acc[i][j][3] * alpha};
                *(float2*)(Cz + (size_t)row * ldc + col) = v0;
                *(float2*)(Cz + (size_t)(row + 8) * ldc + col) = v1;
            } else {
                const float b0 = bias[col], b1 = bias[col + 1];
                float t00 = acc[i][j][0] + b0, t01 = acc[i][j][1] + b1;
                float t10 = acc[i][j][2] + b0, t11 = acc[i][j][3] + b1;
                hf h00 = __float2half(t00), h01 = __float2half(t01);
                hf h10 = __float2half(t10), h11 = __float2half(t11);
                float l00 = t00 - __half2float(h00), l01 = t01 - __half2float(h01);
                float l10 = t10 - __half2float(h10), l11 = t11 - __half2float(h11);
                uint32_t hp0, hp1;
                { __half2 t = {h00, h01}; hp0 = *(uint32_t*)&t; }
                { __half2 t = {h10, h11}; hp1 = *(uint32_t*)&t; }
                *(uint32_t*)(Oh + (size_t)row * ldc + col) = hp0;
                *(uint32_t*)(Oh + (size_t)(row + 8) * ldc + col) = hp1;
                *(uint32_t*)(Ol + (size_t)row * ldc + col) = pack_h2(l00, l01);
                *(uint32_t*)(Ol + (size_t)(row + 8) * ldc + col) = pack_h2(l10, l11);
            }
        }
    }
}

// ---------------- fused prep: split x + [Wq;Wk;Wv] hi/lo, concat bias ------
#define N_X4 (NTD / 4)
#define N_W4 (WSZ / 4)
#define N_B4 (QKV / 4)
#define PREP_TOT (N_X4 + 3 * N_W4 + N_B4)

__global__ __launch_bounds__(256) void prep_k(
    const float* __restrict__ x,
    const float* __restrict__ Wq, const float* __restrict__ Wk, const float* __restrict__ Wv,
    const float* __restrict__ bq, const float* __restrict__ bk, const float* __restrict__ bv,
    hf* __restrict__ xh, hf* __restrict__ xl,
    hf* __restrict__ wch, hf* __restrict__ wcl,
    float* __restrict__ bias)
{
    size_t i = (size_t)blockIdx.x * 256 + threadIdx.x;
    if (i >= PREP_TOT) return;

    if (i >= (size_t)N_X4 + 3 * N_W4) {
        const int j = (int)(i - ((size_t)N_X4 + 3 * N_W4)) * 4;
        float4 o;
        float* po = (float*)&o;
#pragma unroll
        for (int e = 0; e < 4; e++) {
            const int c = j + e;
            po[e] = (c < DIM) ? bq[c] : (c < 2 * DIM) ? bk[c - DIM] : bv[c - 2 * DIM];
        }
        *(float4*)(bias + j) = o;
        return;
    }

    const float* src;
    size_t off;
    hf *dh, *dl;
    if (i < N_X4) { src = x; off = i; dh = xh; dl = xl; }
    else {
        size_t r = i - N_X4;
        const int w = (int)(r / N_W4);
        off = r - (size_t)w * N_W4;
        src = (w == 0) ? Wq : (w == 1) ? Wk : Wv;
        dh = wch + (size_t)w * WSZ; dl = wcl + (size_t)w * WSZ;
    }
    float4 v = ((const float4*)src)[off];
    float vv[4] = {v.x, v.y, v.z, v.w};
    union { unsigned short u[4]; uint2 q; } hh, ll;
#pragma unroll
    for (int e = 0; e < 4; e++) {
        hf hb = __float2half(vv[e]);
        hf lb = __float2half(vv[e] - __half2float(hb));
        hh.u[e] = *(unsigned short*)&hb;
        ll.u[e] = *(unsigned short*)&lb;
    }
    ((uint2*)dh)[off] = hh.q;
    ((uint2*)dl)[off] = ll.q;
}

// ---------------- transpose Vh[b][s][d](ldin) -> Vt[b][d][s] ----------------
__global__ void transpose_k(const hf* __restrict__ vh, hf* __restrict__ th, int ldin)
{
    __shared__ hf sh[32][33];
    const int z = blockIdx.z;
    const size_t ibi = (size_t)z * SEQ * ldin;
    const size_t ibo = (size_t)z * SEQ * DIM;
    const int d0 = blockIdx.x * 32, s0 = blockIdx.y * 32;
    const int tx = threadIdx.x, ty = threadIdx.y;
#pragma unroll
    for (int i = 0; i < 32; i += 8)
        sh[ty + i][tx] = vh[ibi + (size_t)(s0 + ty + i) * ldin + d0 + tx];
    __syncthreads();
#pragma unroll
    for (int i = 0; i < 32; i += 8)
        th[ibo + (size_t)(d0 + ty + i) * SEQ + s0 + tx] = sh[tx][ty + i];
}

// ---------------- softmax: fp32 scores row -> (1024*P) fp16 ----------------
__global__ __launch_bounds__(256) void softmax_k(const float* __restrict__ S,
                                                 hf* __restrict__ ph)
{
    const size_t rb = (size_t)blockIdx.x * SEQ;
    const float* p = S + rb;
    const int tid = threadIdx.x;

    float4 v[4];
#pragma unroll
    for (int i = 0; i < 4; i++) v[i] = *(const float4*)(p + tid * 4 + i * 1024);

    float m = -INFINITY;
#pragma unroll
    for (int i = 0; i < 4; i++)
        m = fmaxf(m, fmaxf(fmaxf(v[i].x, v[i].y), fmaxf(v[i].z, v[i].w)));

    __shared__ float red[256];
    red[tid] = m; __syncthreads();
#pragma unroll
    for (int s = 128; s > 0; s >>= 1) {
        if (tid < s) red[tid] = fmaxf(red[tid], red[tid + s]);
        __syncthreads();
    }
    m = red[0]; __syncthreads();

    float sum = 0.0f;
#pragma unroll
    for (int i = 0; i < 4; i++) {
        v[i].x = fexp(v[i].x - m); v[i].y = fexp(v[i].y - m);
        v[i].z = fexp(v[i].z - m); v[i].w = fexp(v[i].w - m);
        sum += v[i].x + v[i].y + v[i].z + v[i].w;
    }
    red[tid] = sum; __syncthreads();
#pragma unroll
    for (int s = 128; s > 0; s >>= 1) {
        if (tid < s) red[tid] += red[tid + s];
        __syncthreads();
    }
    const float inv = 1024.0f / red[0];        // scaled: keeps fp16 rounding benign

#pragma unroll
    for (int i = 0; i < 4; i++) {
        union { unsigned short u[4]; uint2 q; } hh;
        float vv[4] = {v[i].x * inv, v[i].y * inv, v[i].z * inv, v[i].w * inv};
#pragma unroll
        for (int e = 0; e < 4; e++) {
            hf hb = __float2half(vv[e]);
            hh.u[e] = *(unsigned short*)&hb;
        }
        *(uint2*)(ph + rb + tid * 4 + i * 1024) = hh.q;
    }
}

// ---------------- launch ----------------
extern "C" void kernel_launch(void* const* d_in, const int* in_sizes, int n_in,
                              void* d_out, int out_size)
{
    const float* x  = (const float*)d_in[0];
    const float* Wq = (const float*)d_in[1];
    const float* bq = (const float*)d_in[2];
    const float* Wk = (const float*)d_in[3];
    const float* bk = (const float*)d_in[4];
    const float* Wv = (const float*)d_in[5];
    const float* bv = (const float*)d_in[6];
    float* out = (float*)d_out;

    hf *xh, *xl, *wch, *wcl, *qkvh, *qkvl, *vth, *pph;
    float *sc, *bias;
    cudaGetSymbolAddress((void**)&xh, g_xh);     cudaGetSymbolAddress((void**)&xl, g_xl);
    cudaGetSymbolAddress((void**)&wch, g_wch);   cudaGetSymbolAddress((void**)&wcl, g_wcl);
    cudaGetSymbolAddress((void**)&qkvh, g_qkvh); cudaGetSymbolAddress((void**)&qkvl, g_qkvl);
    cudaGetSymbolAddress((void**)&vth, g_vth);
    cudaGetSymbolAddress((void**)&pph, g_ph);
    cudaGetSymbolAddress((void**)&sc, g_s);      cudaGetSymbolAddress((void**)&bias, g_bias);

    cudaFuncSetAttribute((void*)gemm_mma<0, 1>, cudaFuncAttributeMaxDynamicSharedMemorySize, GEMM_SMEM);
    cudaFuncSetAttribute((void*)gemm_mma<0, 2>, cudaFuncAttributeMaxDynamicSharedMemorySize, GEMM_SMEM);
    cudaFuncSetAttribute((void*)gemm_mma<1, 3>, cudaFuncAttributeMaxDynamicSharedMemorySize, GEMM_SMEM);

    const float scale = 1.0f / sqrtf((float)DIM);

    // 1. fused prep: fp16 hi/lo splits + bias concat
    prep_k<<<(int)((PREP_TOT + 255) / 256), 256>>>(
        x, Wq, Wk, Wv, bq, bk, bv, xh, xl, wch, wcl, bias);

    // 2. fused QKV projection (3-pass, ~exact): [16384,2304] = X*Wc^T + bias
    gemm_mma<1, 3><<<dim3(NTOK / BM, QKV / BN, 1), 256, GEMM_SMEM>>>(
        xh, xl, wch, wcl, nullptr, bias, qkvh, qkvl,
        DIM, DIM, DIM, QKV, 1.0f, 0, 0, 0);

    // 3. transpose V hi (qkv cols 1536..2303) -> Vt[b][d][s]
    transpose_k<<<dim3(DIM / 32, SEQ / 32, BATCH), dim3(32, 8)>>>(
        qkvh + 2 * DIM, vth, QKV);

    // 4. scores[b] = scale * Q[b] K[b]^T   (2-pass: Q exact, K single fp16)
    gemm_mma<0, 2><<<dim3(SEQ / BM, SEQ / BN, BATCH), 256, GEMM_SMEM>>>(
        qkvh, qkvl, qkvh + DIM, qkvh + DIM, sc, nullptr, nullptr, nullptr,
        DIM, QKV, QKV, SEQ, scale,
        (size_t)SEQ * QKV, (size_t)SEQ * QKV, (size_t)SEQ * SEQ);

    // 5. softmax rows -> (1024*P) fp16 (hi only)
    softmax_k<<<NTOK, 256>>>(sc, pph);

    // 6. out[b] = (1/1024) * P[b] V[b]   (1-pass fp16)
    gemm_mma<0, 1><<<dim3(SEQ / BM, DIM / BN, BATCH), 256, GEMM_SMEM>>>(
        pph, pph, vth, vth, out, nullptr, nullptr, nullptr,
        SEQ, SEQ, SEQ, DIM, 1.0f / 1024.0f,
        (size_t)SEQ * SEQ, (size_t)SEQ * DIM, (size_t)SEQ * DIM);

    (void)in_sizes; (void)n_in; (void)out_size;
}